// round 17
// baseline (speedup 1.0000x reference)
#include <cuda_runtime.h>
#include <cuda_bf16.h>
#include <cstdint>

// ============================================================================
// out = patches @ (w_patch @ [w_reg|w_obj]) + bias, anchor decode.
// ONE persistent kernel (graph-node cost ~3.5us each — count matters):
//   phase 1: W2 partials (CTAs 0..383: 24 row-groups x 16 d-chunks of 48)
//   grid barrier 1 (self-resetting counters, proven pattern)
//   phase 2: reduce 16 partials -> bf16 px-permuted HMMA frags (512 x 18)
//   grid barrier 2
//   phase 3: 4 GEMM tiles per CTA (2048 = 512*4, perfectly balanced),
//            R16-proven mainloop (K-split x4, N-split x2, px-permuted A
//            as 2xLDG.128 __ldcs, B 1-ahead __ldg) + decode epilogue.
// Co-residency: launch_bounds(256,5) => capacity 740 >= grid 512 (safe).
// ============================================================================

__device__ float g_part[16 * 12 * 768 * 4];              // [p][jq][pc][4]
__device__ __align__(16) unsigned int g_Bfrag[48 * 6 * 32 * 2];
__device__ unsigned int g_c1, g_c2, g_c3;                // self-reset each run

#define SPART_OFF 0
#define BIAS_OFF  12544
#define TK_OFF    12736
#define TQ_OFF    12800
#define TBW_OFF   12864
#define TBH_OFF   12912
#define SWC_OFF   0            // fold: 48*48 floats = 9216 B
#define SWP_OFF   9216         // fold: 32*49 floats = 6272 B (ends 15488)
#define SMEMB     15488

__global__ void __launch_bounds__(256, 5) kF(
    const float* __restrict__ img,
    const float* __restrict__ w_patch,
    const float* __restrict__ w_reg,
    const float* __restrict__ b_reg,
    const float* __restrict__ w_obj,
    const float* __restrict__ b_obj,
    float* __restrict__ out)
{
    extern __shared__ __align__(16) char sm[];
    const int tid  = threadIdx.x;
    const int wid  = tid >> 5;
    const int lane = tid & 31;
    const int bid  = blockIdx.x;

    // ---- phase 1: W2 partials (CTAs 0..383) ----
    if (bid < 384) {
        const int rg = bid % 24, ch = bid / 24;   // ch 0..15
        const int r0 = rg * 32, d0 = ch * 48;
        float* sWc = (float*)(sm + SWC_OFF);
        float* sWp = (float*)(sm + SWP_OFF);
        for (int i = tid; i < 48 * 48; i += 256) {
            int d = i / 48, j = i % 48;
            float v = 0.f;
            if (j < 36)       v = w_reg[(size_t)(d0 + d) * 36 + j];
            else if (j < 45)  v = w_obj[(size_t)(d0 + d) * 9 + (j - 36)];
            sWc[i] = v;
        }
        for (int i = tid; i < 32 * 48; i += 256) {
            int r = i / 48, d = i % 48;
            sWp[r * 49 + d] = w_patch[(size_t)(r0 + r) * 768 + d0 + d];
        }
        __syncthreads();
        const int rl = tid & 31;
        for (int jq = wid; jq < 12; jq += 8) {    // warp-uniform broadcast
            float4 acc = make_float4(0.f, 0.f, 0.f, 0.f);
            #pragma unroll 8
            for (int dd = 0; dd < 48; ++dd) {
                float4 w = *(const float4*)&sWc[dd * 48 + jq * 4];
                float  a = sWp[rl * 49 + dd];
                acc.x += a * w.x; acc.y += a * w.y;
                acc.z += a * w.z; acc.w += a * w.w;
            }
            ((float4*)g_part)[((size_t)ch * 12 + jq) * 768 + r0 + rl] = acc;
        }
    }

    // ---- grid barrier 1 (512 CTAs, capacity 740 — safe) ----
    __threadfence();
    __syncthreads();
    if (tid == 0) {
        atomicAdd(&g_c1, 1u);
        while (*(volatile unsigned int*)&g_c1 < 512u) { }
    }
    __syncthreads();
    __threadfence();

    // ---- phase 2: reduce 16 partials, scatter bf16 frags (512 x 18) ----
    if (tid < 18) {
        const int o   = bid * 18 + tid;           // 0..9215
        const int pc  = o % 768;
        const int jqo = o / 768;
        const float4* p4 = (const float4*)g_part;
        float4 s = make_float4(0.f, 0.f, 0.f, 0.f);
        #pragma unroll
        for (int p = 0; p < 16; ++p) {
            float4 v = p4[(size_t)p * 9216 + o];
            s.x += v.x; s.y += v.y; s.z += v.z; s.w += v.w;
        }
        float sv[4] = {s.x, s.y, s.z, s.w};
        const int st = pc >> 4, px = pc & 15;
        const int q = px & 3, t4p = px >> 2;
        const int k = (q < 2) ? (2 * t4p + q) : (8 + 2 * t4p + (q - 2));
        unsigned short* dst = (unsigned short*)g_Bfrag;
        #pragma unroll
        for (int c = 0; c < 4; ++c) {
            int j = jqo * 4 + c;
            int tf = j >> 3;
            int ln = ((j & 7) << 2) | ((k >> 1) & 3);
            __nv_bfloat16 v = __float2bfloat16_rn(sv[c]);
            dst[(((st * 6 + tf) * 32 + ln) * 2 + (k >> 3)) * 2 + (k & 1)] =
                *(unsigned short*)&v;
        }
    }

    // ---- grid barrier 2 ----
    __threadfence();
    __syncthreads();
    if (tid == 0) {
        atomicAdd(&g_c2, 1u);
        while (*(volatile unsigned int*)&g_c2 < 512u) { }
    }
    __syncthreads();
    __threadfence();

    // ---- bias + decode tables (after fold smem is dead) ----
    if (tid < 48) ((float*)(sm + BIAS_OFF))[tid] =
        (tid < 36) ? b_reg[tid] : ((tid < 45) ? b_obj[tid - 36] : 0.f);
    if (tid < 63) {
        ((unsigned char*)(sm + TK_OFF))[tid] = (unsigned char)(tid / 7);
        ((unsigned char*)(sm + TQ_OFF))[tid] = (unsigned char)(tid % 7);
    }
    if (tid < 9) {
        ((float*)(sm + TBW_OFF))[tid] = (float)(2 << (tid % 3));
        ((float*)(sm + TBH_OFF))[tid] = (float)(2 << (tid / 3));
    }
    __syncthreads();

    // ---- phase 3: 4 GEMM tiles (R16-proven mainloop + epilogue) ----
    const int ks = wid >> 1;
    const int ns = wid & 1;
    const int g  = lane >> 2;
    const int t4 = lane & 3;
    const int s0 = ks * 12;
    const uint2* __restrict__ Bf = (const uint2*)g_Bfrag;

    #define SOFF(s) ((size_t)((((s) >> 4) << 9) + ((s) & 15)) << 9)

    #define LOADA(d0_, d1_, s) do {                  \
        const float* p_ = base + SOFF(s);            \
        d0_ = __ldcs((const float4*)(p_));           \
        d1_ = __ldcs((const float4*)(p_ + 128));     \
    } while (0)

    #define LOADB(B_, s) do {                                    \
        _Pragma("unroll")                                        \
        for (int t_ = 0; t_ < 3; ++t_)                           \
            B_[t_] = __ldg(&Bf[((s) * 6 + ns * 3 + t_) * 32 + lane]); \
    } while (0)

    #define COMPUTE(f0_, f1_, B_) do {                                        \
        uint32_t a0_, a1_, a2_, a3_;                                          \
        { __nv_bfloat162 h_ = __float22bfloat162_rn(make_float2(f0_.x, f0_.y)); a0_ = *(uint32_t*)&h_; } \
        { __nv_bfloat162 h_ = __float22bfloat162_rn(make_float2(f1_.x, f1_.y)); a1_ = *(uint32_t*)&h_; } \
        { __nv_bfloat162 h_ = __float22bfloat162_rn(make_float2(f0_.z, f0_.w)); a2_ = *(uint32_t*)&h_; } \
        { __nv_bfloat162 h_ = __float22bfloat162_rn(make_float2(f1_.z, f1_.w)); a3_ = *(uint32_t*)&h_; } \
        _Pragma("unroll")                                                     \
        for (int t_ = 0; t_ < 3; ++t_)                                        \
            asm volatile(                                                     \
                "mma.sync.aligned.m16n8k16.row.col.f32.bf16.bf16.f32 "        \
                "{%0,%1,%2,%3}, {%4,%5,%6,%7}, {%8,%9}, {%0,%1,%2,%3};"       \
                : "+f"(d[t_][0]), "+f"(d[t_][1]), "+f"(d[t_][2]), "+f"(d[t_][3]) \
                : "r"(a0_), "r"(a1_), "r"(a2_), "r"(a3_),                     \
                  "r"(B_[t_].x), "r"(B_[t_].y));                              \
    } while (0)

    #pragma unroll 1
    for (int ti = 0; ti < 4; ++ti) {
        const int t  = bid + 512 * ti;
        const int cg = t & 1;
        const int fy = (t >> 1) & 31;
        const int b  = t >> 6;

        const float* base = img + ((size_t)(b * 3) * 512 + (size_t)fy * 16) * 512
                          + (cg * 16 + g) * 16 + 4 * t4;

        float d[3][4];
        #pragma unroll
        for (int tt = 0; tt < 3; ++tt)
            #pragma unroll
            for (int q = 0; q < 4; ++q) d[tt][q] = 0.f;

        float4 A0a, A0b, A1a, A1b;
        uint2  B0[3], B1[3];
        LOADA(A0a, A0b, s0);
        LOADA(A1a, A1b, s0 + 1);
        LOADB(B0, s0);

        #pragma unroll
        for (int i = 0; i < 6; ++i) {
            const int s  = s0 + 2 * i;
            const int n0 = (2 * i + 2 < 12) ? s + 2 : s0 + 11;
            const int n1 = (2 * i + 3 < 12) ? s + 3 : s0 + 11;
            LOADB(B1, s + 1);
            COMPUTE(A0a, A0b, B0);
            LOADA(A0a, A0b, n0);
            LOADB(B0, n0);
            COMPUTE(A1a, A1b, B1);
            LOADA(A1a, A1b, n1);
        }

        // ---- epilogue: partials to sPart[ks][16][49] ----
        float* sPart = (float*)(sm + SPART_OFF);
        float* sBias = (float*)(sm + BIAS_OFF);
        #pragma unroll
        for (int cc = 0; cc < 2; ++cc) {
            const int cell = g + cc * 8;
            float* dst = sPart + (ks * 16 + cell) * 49;
            #pragma unroll
            for (int tt = 0; tt < 3; ++tt) {
                const int j = (ns * 3 + tt) * 8 + t4 * 2;
                dst[j]     = d[tt][2 * cc];
                dst[j + 1] = d[tt][2 * cc + 1];
            }
        }
        __syncthreads();

        #pragma unroll
        for (int i = 0; i < 4; ++i) {
            int idx = tid + 256 * i;
            if (idx < 16 * 49) {
                int j = idx % 49;
                if (j < 48) {
                    sPart[idx] = sPart[idx] + sPart[idx + 16 * 49]
                               + sPart[idx + 2 * 16 * 49] + sPart[idx + 3 * 16 * 49]
                               + sBias[j];
                }
            }
        }
        __syncthreads();

        const unsigned char* tK = (const unsigned char*)(sm + TK_OFF);
        const unsigned char* tQ = (const unsigned char*)(sm + TQ_OFF);
        const float* tBW = (const float*)(sm + TBW_OFF);
        const float* tBH = (const float*)(sm + TBH_OFF);
        float* obase = out + (size_t)t * 1008;
        const float bb_f = (float)b;
        const float fy_f = (float)fy * 16.f;
        const float fx0  = (float)(cg * 16);

        int cell = tid / 63;
        int r    = tid - cell * 63;
        int idx  = tid;
        #pragma unroll
        for (int i = 0; i < 4; ++i) {
            if (idx < 1008) {
                const int k = tK[r], q = tQ[r];
                const float* v = sPart + cell * 49;
                float res;
                if (q == 0)      res = (fx0 + (float)cell) * 16.f + v[4 * k];
                else if (q == 1) res = fy_f + v[4 * k + 1];
                else if (q == 2) res = (fx0 + (float)cell) * 16.f + v[4 * k] + tBW[k] * v[4 * k + 2];
                else if (q == 3) res = fy_f + v[4 * k + 1] + tBH[k] * v[4 * k + 3];
                else if (q == 4) res = bb_f;
                else if (q == 5) res = 1.f / (1.f + __expf(-v[36 + k]));
                else             res = (float)k;
                obase[idx] = res;
            }
            idx += 256; r += 4; cell += 4;
            if (r >= 63) { r -= 63; cell++; }
        }
        __syncthreads();   // protect sPart before next tile's scatter
    }

    // ---- completion; last CTA resets counters for next replay ----
    if (tid == 0) {
        __threadfence();
        unsigned int r = atomicAdd(&g_c3, 1u);
        if (r == 511u) {
            atomicExch(&g_c1, 0u);
            atomicExch(&g_c2, 0u);
            atomicExch(&g_c3, 0u);
        }
    }
}

// ---------------------------------------------------------------------------
extern "C" void kernel_launch(void* const* d_in, const int* in_sizes, int n_in,
                              void* d_out, int out_size)
{
    const float* img     = (const float*)d_in[0];
    const float* w_patch = (const float*)d_in[1];
    const float* w_reg   = (const float*)d_in[2];
    const float* b_reg   = (const float*)d_in[3];
    const float* w_obj   = (const float*)d_in[4];
    const float* b_obj   = (const float*)d_in[5];
    float* out = (float*)d_out;

    kF<<<512, 256, SMEMB>>>(img, w_patch, w_reg, b_reg, w_obj, b_obj, out);
}